// round 16
// baseline (speedup 1.0000x reference)
#include <cuda_runtime.h>

#define NN 32
#define DS 33                           // D stride (33 physical slots)
#define CC 1024
#define NT 512
#define FULLM 0xffffffffu

// dynamic smem layout
#define OFF_ROWS 0                      // float [33][1024]  = 135168
#define OFF_D    135168                 // float [33][33]    = 4356 -> pad 4480
#define OFF_VAL  139648                 // u32   [2][32]     = 256
#define OFF_IDX  139904                 // u32   [2][32]     = 256
#define OFF_SQ   140160                 // float [33]        = 132 -> pad 160
#define OFF_L    140320                 // int   [2][32]     = 256
#define SMEM_TOTAL 140576

typedef unsigned long long u64;

__device__ __forceinline__ float warp_sum(float v) {
    #pragma unroll
    for (int o = 16; o; o >>= 1) v += __shfl_down_sync(FULLM, v, o);
    return v;
}

__device__ __forceinline__ void warp_sum3(float& a, float& b, float& c) {
    #pragma unroll
    for (int o = 16; o; o >>= 1) {
        a += __shfl_down_sync(FULLM, a, o);
        b += __shfl_down_sync(FULLM, b, o);
        c += __shfl_down_sync(FULLM, c, o);
    }
}

__device__ __forceinline__ void warp_sum4(float& a, float& b, float& c, float& d) {
    #pragma unroll
    for (int o = 16; o; o >>= 1) {
        a += __shfl_down_sync(FULLM, a, o);
        b += __shfl_down_sync(FULLM, b, o);
        c += __shfl_down_sync(FULLM, c, o);
        d += __shfl_down_sync(FULLM, d, o);
    }
}

// conv chain EXACTLY as previous rounds (bit-identical)
__device__ __forceinline__ float conv1(float a0, float a1, float a2,
                                       float b0, float b1, float b2,
                                       float w00, float w01, float w02,
                                       float w10, float w11, float w12, float bv) {
    float m = fmaf(w00, a0, fmaf(w01, a1, fmaf(w02, a2,
              fmaf(w10, b0, fmaf(w11, b1, fmaf(w12, b2, bv))))));
    return fmaxf(m, 0.f);
}

__global__ __launch_bounds__(NT, 1)
void merge_tree_kernel(const float* __restrict__ x,
                       const float* __restrict__ cw,
                       const float* __restrict__ cb,
                       float* __restrict__ out)
{
    extern __shared__ unsigned char sm_raw[];
    float*    rows = (float*)(sm_raw + OFF_ROWS);
    float*    D    = (float*)(sm_raw + OFF_D);        // [33][33], stride DS
    unsigned* vals = (unsigned*)(sm_raw + OFF_VAL);   // [2][32] (16 used)
    unsigned* idxs = (unsigned*)(sm_raw + OFF_IDX);
    float*    sq   = (float*)(sm_raw + OFF_SQ);       // [33]
    int*      Lb   = (int*)(sm_raw + OFF_L);          // [2][32]

    const int tid  = threadIdx.x;
    const int lane = tid & 31;
    const int warp = tid >> 5;                        // 0..15
    const int b    = blockIdx.x;

    // ---- load batch rows (coalesced float4) ----
    {
        const float4* xb4 = (const float4*)(x + (size_t)b * (NN * CC));
        float4* r4 = (float4*)rows;
        #pragma unroll
        for (int i = tid; i < NN * CC / 4; i += NT) r4[i] = xb4[i];
    }
    const float w00 = cw[0], w01 = cw[1], w02 = cw[2];
    const float w10 = cw[3], w11 = cw[4], w12 = cw[5];
    const float bv  = cb[0];
    if (tid < NN) Lb[tid] = tid;                      // L buffer 0
    __syncthreads();

    // ---- cache TWO rows per warp (2I, 2I+1); norms + diag dot ----
    float4 c0[8], c1[8];
    float diagdot;                                    // valid on lane 0
    {
        const float4* r0 = (const float4*)(rows + (2 * warp) * CC);
        const float4* r1 = (const float4*)(rows + (2 * warp + 1) * CC);
        #pragma unroll
        for (int k = 0; k < 8; k++) { c0[k] = r0[lane + 32 * k]; c1[k] = r1[lane + 32 * k]; }

        float n0a=0,n0b=0,n0c=0,n0d=0;
        float n1a=0,n1b=0,n1c=0,n1d=0;
        float dda=0,ddb=0,ddc=0,ddd=0;
        #pragma unroll
        for (int k = 0; k < 8; k++) {
            n0a = fmaf(c0[k].x, c0[k].x, n0a);
            n0b = fmaf(c0[k].y, c0[k].y, n0b);
            n0c = fmaf(c0[k].z, c0[k].z, n0c);
            n0d = fmaf(c0[k].w, c0[k].w, n0d);
            n1a = fmaf(c1[k].x, c1[k].x, n1a);
            n1b = fmaf(c1[k].y, c1[k].y, n1b);
            n1c = fmaf(c1[k].z, c1[k].z, n1c);
            n1d = fmaf(c1[k].w, c1[k].w, n1d);
            dda = fmaf(c0[k].x, c1[k].x, dda);
            ddb = fmaf(c0[k].y, c1[k].y, ddb);
            ddc = fmaf(c0[k].z, c1[k].z, ddc);
            ddd = fmaf(c0[k].w, c1[k].w, ddd);
        }
        float s0 = (n0a + n0b) + (n0c + n0d);
        float s1 = (n1a + n1b) + (n1c + n1d);
        float sd = (dda + ddb) + (ddc + ddd);
        warp_sum3(s0, s1, sd);
        if (!lane) { sq[2 * warp] = s0; sq[2 * warp + 1] = s1; }
        diagdot = sd;
    }
    __syncthreads();                                  // sq[] visible

    if (!lane) {
        int i = 2 * warp, j = 2 * warp + 1;
        float d2v = sq[i] + sq[j] - 2.0f * diagdot;
        float d = sqrtf(fmaxf(d2v, 0.f));
        D[i * DS + j] = d;
        D[j * DS + i] = d;
    }

    // ---- gram off-diag: supertile rotation, 2x2 tiles ----
    {
        #pragma unroll 1
        for (int k = 1; k <= 8; k++) {
            if (k == 8 && warp >= 8) break;
            const int J = (warp + k) & 15;
            const float4* v0p = (const float4*)(rows + (2 * J) * CC);
            const float4* v1p = (const float4*)(rows + (2 * J + 1) * CC);
            float p00a=0,p00b=0,p00c=0,p00d=0;
            float p01a=0,p01b=0,p01c=0,p01d=0;
            float p10a=0,p10b=0,p10c=0,p10d=0;
            float p11a=0,p11b=0,p11c=0,p11d=0;
            #pragma unroll
            for (int q = 0; q < 8; q++) {
                float4 v0 = v0p[lane + 32 * q];
                float4 v1 = v1p[lane + 32 * q];
                p00a = fmaf(c0[q].x, v0.x, p00a);
                p00b = fmaf(c0[q].y, v0.y, p00b);
                p00c = fmaf(c0[q].z, v0.z, p00c);
                p00d = fmaf(c0[q].w, v0.w, p00d);
                p01a = fmaf(c0[q].x, v1.x, p01a);
                p01b = fmaf(c0[q].y, v1.y, p01b);
                p01c = fmaf(c0[q].z, v1.z, p01c);
                p01d = fmaf(c0[q].w, v1.w, p01d);
                p10a = fmaf(c1[q].x, v0.x, p10a);
                p10b = fmaf(c1[q].y, v0.y, p10b);
                p10c = fmaf(c1[q].z, v0.z, p10c);
                p10d = fmaf(c1[q].w, v0.w, p10d);
                p11a = fmaf(c1[q].x, v1.x, p11a);
                p11b = fmaf(c1[q].y, v1.y, p11b);
                p11c = fmaf(c1[q].z, v1.z, p11c);
                p11d = fmaf(c1[q].w, v1.w, p11d);
            }
            float s00 = (p00a + p00b) + (p00c + p00d);
            float s01 = (p01a + p01b) + (p01c + p01d);
            float s10 = (p10a + p10b) + (p10c + p10d);
            float s11 = (p11a + p11b) + (p11c + p11d);
            warp_sum4(s00, s01, s10, s11);
            if (!lane) {
                int i0 = 2 * warp, i1 = 2 * warp + 1, j0 = 2 * J, j1 = 2 * J + 1;
                float e00 = sqrtf(fmaxf(sq[i0] + sq[j0] - 2.0f * s00, 0.f));
                float e01 = sqrtf(fmaxf(sq[i0] + sq[j1] - 2.0f * s01, 0.f));
                float e10 = sqrtf(fmaxf(sq[i1] + sq[j0] - 2.0f * s10, 0.f));
                float e11 = sqrtf(fmaxf(sq[i1] + sq[j1] - 2.0f * s11, 0.f));
                D[i0 * DS + j0] = e00; D[j0 * DS + i0] = e00;
                D[i0 * DS + j1] = e01; D[j1 * DS + i0] = e01;
                D[i1 * DS + j0] = e10; D[j0 * DS + i1] = e10;
                D[i1 * DS + j1] = e11; D[j1 * DS + i1] = e11;
            }
        }
    }
    __syncthreads();                                  // D complete

    // ---- pre-loop argmin partials: warp w scans rows w and w+16 ----
    {
        u64 kk = 0xffffffffffffffffull;
        {
            unsigned kv = (lane > warp) ? __float_as_uint(D[warp * DS + lane]) : FULLM;
            unsigned wv = __reduce_min_sync(FULLM, kv);
            unsigned mm = __ballot_sync(FULLM, kv == wv);
            if (wv != FULLM) {
                int jw = __ffs(mm) - 1;
                kk = ((u64)wv << 32) | (unsigned)((warp << 5) | jw);
            }
        }
        {
            const int i = warp + 16;
            if (i <= NN - 2) {
                unsigned kv = (lane > i) ? __float_as_uint(D[i * DS + lane]) : FULLM;
                unsigned wv = __reduce_min_sync(FULLM, kv);
                unsigned mm = __ballot_sync(FULLM, kv == wv);
                if (wv != FULLM) {
                    int jw = __ffs(mm) - 1;
                    u64 kc = ((u64)wv << 32) | (unsigned)((i << 5) | jw);
                    kk = min(kk, kc);
                }
            }
        }
        if (!lane) { vals[warp] = (unsigned)(kk >> 32); idxs[warp] = (unsigned)(kk & 0x3ffu); }
    }
    __syncthreads();

    // ==== 31 merge steps, 2 barriers each ====
    int n = NN;
    int par = 0;
    int lpar = 0;
    int spare = 32;
    const int h0 = tid, h1 = tid + NT;
    for (int step = 0; step < NN - 1; step++, n--) {
        unsigned* vcur = vals + par * 32;
        unsigned* icur = idxs + par * 32;
        par ^= 1;
        unsigned* vnxt = vals + par * 32;
        unsigned* inxt = idxs + par * 32;
        int* Lcur = Lb + lpar * 32;
        lpar ^= 1;
        int* Lnxt = Lb + lpar * 32;

        // ---------- P1: combine, then conv (warps 0-7) || scan (warps 8-15) --
        unsigned v  = (lane < 16) ? vcur[lane] : FULLM;
        unsigned gm = __reduce_min_sync(FULLM, v);
        unsigned mk = __ballot_sync(FULLM, v == gm);
        unsigned cd = ((mk >> lane) & 1) ? icur[lane] : FULLM;
        unsigned gi = __reduce_min_sync(FULLM, cd);

        const int a   = (gi >> 5) & 31;
        const int bbj = gi & 31;
        const int ra  = Lcur[a];
        const int rb  = Lcur[bbj];
        const int dst = spare;
        // freed slot: normally L[a]; when a==1 the reference's sequential
        // perm-sets drop logical row 0 and KEEP row 1, so freed slot is L[0].
        spare = (a == 1) ? Lcur[0] : ra;

        const int cnt = n - 2;                        // survivors 1..cnt
        u64 kk = 0xffffffffffffffffull;               // per-warp argmin key

        const float* Xa = rows + ra * CC;
        const float* Xb = rows + rb * CC;

        if (warp < 8) {
            // conv1d(2ch->1ch,k=3,SAME)+bias+relu, FOUR elems/thread (h=4t..4t+3)
            const float4 fa = *(const float4*)(Xa + 4 * tid);
            const float4 fb = *(const float4*)(Xb + 4 * tid);
            float aL = __shfl_up_sync(FULLM, fa.w, 1);
            float bL = __shfl_up_sync(FULLM, fb.w, 1);
            if (lane == 0) {
                aL = (tid > 0) ? Xa[4 * tid - 1] : 0.f;
                bL = (tid > 0) ? Xb[4 * tid - 1] : 0.f;
            }
            float aR = __shfl_down_sync(FULLM, fa.x, 1);
            float bR = __shfl_down_sync(FULLM, fb.x, 1);
            if (lane == 31) {
                aR = (4 * tid + 4 < CC) ? Xa[4 * tid + 4] : 0.f;
                bR = (4 * tid + 4 < CC) ? Xb[4 * tid + 4] : 0.f;
            }
            float4 mo;
            mo.x = conv1(aL,   fa.x, fa.y, bL,   fb.x, fb.y, w00,w01,w02,w10,w11,w12,bv);
            mo.y = conv1(fa.x, fa.y, fa.z, fb.x, fb.y, fb.z, w00,w01,w02,w10,w11,w12,bv);
            mo.z = conv1(fa.y, fa.z, fa.w, fb.y, fb.z, fb.w, w00,w01,w02,w10,w11,w12,bv);
            mo.w = conv1(fa.z, fa.w, aR,   fb.z, fb.w, bR,   w00,w01,w02,w10,w11,w12,bv);
            *(float4*)(rows + dst * CC + 4 * tid) = mo;   // no WAR: dst was spare

            if (tid < n - 1) {                            // threads 0..30 (warp 0)
                int nv;
                if (tid == 0) nv = dst;
                else {
                    int pp  = tid + 1;
                    int src = (pp == a) ? 0 : ((pp == bbj) ? 1 : pp);
                    nv = Lcur[src];
                }
                Lnxt[tid] = nv;
            }
        } else if (cnt > 0) {
            // scan warps 8-15: survivor-survivor argmin partials of next config.
            // Next-config slots computed directly from Lcur (== Lnxt values).
            const int pp   = lane + 1;
            const int srcl = (pp == a) ? 0 : ((pp == bbj) ? 1 : pp);
            const int slvN = (lane >= 1 && lane <= cnt) ? Lcur[srcl] : 0;
            #pragma unroll
            for (int r = 0; r < 4; r++) {
                const int i = (warp - 8) + 1 + 8 * r;
                if (i <= cnt - 1) {
                    const int si = __shfl_sync(FULLM, slvN, i);
                    unsigned kv = FULLM;
                    if (lane > i && lane <= cnt)
                        kv = __float_as_uint(D[si * DS + slvN]);
                    unsigned wv = __reduce_min_sync(FULLM, kv);
                    unsigned mm = __ballot_sync(FULLM, kv == wv);
                    if (wv != FULLM) {
                        int jw = __ffs(mm) - 1;
                        u64 kc = ((u64)wv << 32) | (unsigned)((i << 5) | jw);
                        kk = min(kk, kc);
                    }
                }
            }
        }
        __syncthreads();                              // bar 1: m, Lnxt visible

        // ---------- P2: dots on warps 0-9 (3 survivors, m reg-cached) ----------
        if (cnt > 0) {
            if (warp < 10) {
                const int slv = (lane >= 1 && lane <= cnt) ? Lnxt[lane] : 0;
                const int j0 = 3 * warp;              // 0-based survivor idx
                if (j0 < cnt) {
                    const int c1ok = (j0 + 1) < cnt;
                    const int c2ok = (j0 + 2) < cnt;
                    const int s0 = __shfl_sync(FULLM, slv, 1 + j0);
                    const int s1 = __shfl_sync(FULLM, slv, c1ok ? (2 + j0) : (1 + j0));
                    const int s2 = __shfl_sync(FULLM, slv, c2ok ? (3 + j0) : (1 + j0));
                    float4 mv[8];
                    const float4* rm = (const float4*)(rows + dst * CC);
                    #pragma unroll
                    for (int k = 0; k < 8; k++) mv[k] = rm[lane + 32 * k];

                    const float4* rs0 = (const float4*)(rows + s0 * CC);
                    const float4* rs1 = (const float4*)(rows + s1 * CC);
                    const float4* rs2 = (const float4*)(rows + s2 * CC);
                    float A0=0,A1=0,A2=0,A3=0;
                    float B0=0,B1=0,B2=0,B3=0;
                    float C0=0,C1=0,C2=0,C3=0;
                    float M0=0,M1=0,M2=0,M3=0;
                    #pragma unroll
                    for (int k = 0; k < 8; k++) {
                        float4 u  = mv[k];
                        float4 v0 = rs0[lane + 32 * k];
                        float4 v1 = rs1[lane + 32 * k];
                        float4 v2 = rs2[lane + 32 * k];
                        A0 = fmaf(u.x, v0.x, A0);
                        A1 = fmaf(u.y, v0.y, A1);
                        A2 = fmaf(u.z, v0.z, A2);
                        A3 = fmaf(u.w, v0.w, A3);
                        B0 = fmaf(u.x, v1.x, B0);
                        B1 = fmaf(u.y, v1.y, B1);
                        B2 = fmaf(u.z, v1.z, B2);
                        B3 = fmaf(u.w, v1.w, B3);
                        C0 = fmaf(u.x, v2.x, C0);
                        C1 = fmaf(u.y, v2.y, C1);
                        C2 = fmaf(u.z, v2.z, C2);
                        C3 = fmaf(u.w, v2.w, C3);
                        M0 = fmaf(u.x, u.x, M0);
                        M1 = fmaf(u.y, u.y, M1);
                        M2 = fmaf(u.z, u.z, M2);
                        M3 = fmaf(u.w, u.w, M3);
                    }
                    float d0  = (A0 + A1) + (A2 + A3);
                    float d1  = (B0 + B1) + (B2 + B3);
                    float d2s = (C0 + C1) + (C2 + C3);
                    float msq = (M0 + M1) + (M2 + M3);
                    warp_sum4(d0, d1, d2s, msq);
                    if (!lane) {
                        float e0 = sqrtf(fmaxf(msq + sq[s0] - 2.0f * d0, 0.f));
                        D[dst * DS + s0] = e0;
                        D[s0 * DS + dst] = e0;
                        u64 kd = ((u64)__float_as_uint(e0) << 32) | (unsigned)(1 + j0);
                        kk = min(kk, kd);
                        if (c1ok) {
                            float e1 = sqrtf(fmaxf(msq + sq[s1] - 2.0f * d1, 0.f));
                            D[dst * DS + s1] = e1;
                            D[s1 * DS + dst] = e1;
                            u64 k1 = ((u64)__float_as_uint(e1) << 32) | (unsigned)(2 + j0);
                            kk = min(kk, k1);
                        }
                        if (c2ok) {
                            float e2 = sqrtf(fmaxf(msq + sq[s2] - 2.0f * d2s, 0.f));
                            D[dst * DS + s2] = e2;
                            D[s2 * DS + dst] = e2;
                            u64 k2 = ((u64)__float_as_uint(e2) << 32) | (unsigned)(3 + j0);
                            kk = min(kk, k2);
                        }
                        if (warp == 0) sq[dst] = msq; // persist merged norm
                    }
                }
            }

            if (!lane) {
                vnxt[warp] = (unsigned)(kk >> 32);
                inxt[warp] = (unsigned)(kk & 0x3ffu);
            }
        }
        __syncthreads();                              // bar 2
    }

    // final merged row lives at slot Lfinal[0]
    {
        const int fs = (Lb + lpar * 32)[0];
        out[(size_t)b * CC + h0] = rows[fs * CC + h0];
        out[(size_t)b * CC + h1] = rows[fs * CC + h1];
    }
}

extern "C" void kernel_launch(void* const* d_in, const int* in_sizes, int n_in,
                              void* d_out, int out_size)
{
    const float* x  = (const float*)d_in[0];
    const float* cw = (const float*)d_in[1];
    const float* cb = (const float*)d_in[2];
    float* out = (float*)d_out;

    int B = in_sizes[0] / (NN * CC);

    cudaFuncSetAttribute(merge_tree_kernel,
                         cudaFuncAttributeMaxDynamicSharedMemorySize,
                         SMEM_TOTAL);
    merge_tree_kernel<<<B, NT, SMEM_TOTAL>>>(x, cw, cb, out);
}

// round 17
// speedup vs baseline: 1.1100x; 1.1100x over previous
#include <cuda_runtime.h>

#define NN 32
#define DS 33                           // D stride (33 physical slots)
#define CC 1024
#define NT 512
#define FULLM 0xffffffffu

// dynamic smem layout
#define OFF_ROWS 0                      // float [33][1024]  = 135168
#define OFF_D    135168                 // float [33][33]    = 4356 -> pad 4480
#define OFF_VAL  139648                 // u32   [2][32]     = 256
#define OFF_IDX  139904                 // u32   [2][32]     = 256
#define OFF_SQ   140160                 // float [33]        = 132 -> pad 160
#define OFF_L    140320                 // int   [2][32]     = 256
#define SMEM_TOTAL 140576

typedef unsigned long long u64;

__device__ __forceinline__ float warp_sum(float v) {
    #pragma unroll
    for (int o = 16; o; o >>= 1) v += __shfl_down_sync(FULLM, v, o);
    return v;
}

__device__ __forceinline__ void warp_sum3(float& a, float& b, float& c) {
    #pragma unroll
    for (int o = 16; o; o >>= 1) {
        a += __shfl_down_sync(FULLM, a, o);
        b += __shfl_down_sync(FULLM, b, o);
        c += __shfl_down_sync(FULLM, c, o);
    }
}

__device__ __forceinline__ void warp_sum4(float& a, float& b, float& c, float& d) {
    #pragma unroll
    for (int o = 16; o; o >>= 1) {
        a += __shfl_down_sync(FULLM, a, o);
        b += __shfl_down_sync(FULLM, b, o);
        c += __shfl_down_sync(FULLM, c, o);
        d += __shfl_down_sync(FULLM, d, o);
    }
}

// conv chain EXACTLY as previous rounds (bit-identical)
__device__ __forceinline__ float conv1(float a0, float a1, float a2,
                                       float b0, float b1, float b2,
                                       float w00, float w01, float w02,
                                       float w10, float w11, float w12, float bv) {
    float m = fmaf(w00, a0, fmaf(w01, a1, fmaf(w02, a2,
              fmaf(w10, b0, fmaf(w11, b1, fmaf(w12, b2, bv))))));
    return fmaxf(m, 0.f);
}

__global__ __launch_bounds__(NT, 1)
void merge_tree_kernel(const float* __restrict__ x,
                       const float* __restrict__ cw,
                       const float* __restrict__ cb,
                       float* __restrict__ out)
{
    extern __shared__ unsigned char sm_raw[];
    float*    rows = (float*)(sm_raw + OFF_ROWS);
    float*    D    = (float*)(sm_raw + OFF_D);        // [33][33], stride DS
    unsigned* vals = (unsigned*)(sm_raw + OFF_VAL);   // [2][32] (16 used)
    unsigned* idxs = (unsigned*)(sm_raw + OFF_IDX);
    float*    sq   = (float*)(sm_raw + OFF_SQ);       // [33]
    int*      Lb   = (int*)(sm_raw + OFF_L);          // [2][32]

    const int tid  = threadIdx.x;
    const int lane = tid & 31;
    const int warp = tid >> 5;                        // 0..15
    const int b    = blockIdx.x;

    // ---- load batch rows (coalesced float4) ----
    {
        const float4* xb4 = (const float4*)(x + (size_t)b * (NN * CC));
        float4* r4 = (float4*)rows;
        #pragma unroll
        for (int i = tid; i < NN * CC / 4; i += NT) r4[i] = xb4[i];
    }
    const float w00 = cw[0], w01 = cw[1], w02 = cw[2];
    const float w10 = cw[3], w11 = cw[4], w12 = cw[5];
    const float bv  = cb[0];
    if (tid < NN) Lb[tid] = tid;                      // L buffer 0
    __syncthreads();

    // ---- cache TWO rows per warp (2I, 2I+1); norms + diag dot ----
    float4 c0[8], c1[8];
    float diagdot;                                    // valid on lane 0
    {
        const float4* r0 = (const float4*)(rows + (2 * warp) * CC);
        const float4* r1 = (const float4*)(rows + (2 * warp + 1) * CC);
        #pragma unroll
        for (int k = 0; k < 8; k++) { c0[k] = r0[lane + 32 * k]; c1[k] = r1[lane + 32 * k]; }

        float n0a=0,n0b=0,n0c=0,n0d=0;
        float n1a=0,n1b=0,n1c=0,n1d=0;
        float dda=0,ddb=0,ddc=0,ddd=0;
        #pragma unroll
        for (int k = 0; k < 8; k++) {
            n0a = fmaf(c0[k].x, c0[k].x, n0a);
            n0b = fmaf(c0[k].y, c0[k].y, n0b);
            n0c = fmaf(c0[k].z, c0[k].z, n0c);
            n0d = fmaf(c0[k].w, c0[k].w, n0d);
            n1a = fmaf(c1[k].x, c1[k].x, n1a);
            n1b = fmaf(c1[k].y, c1[k].y, n1b);
            n1c = fmaf(c1[k].z, c1[k].z, n1c);
            n1d = fmaf(c1[k].w, c1[k].w, n1d);
            dda = fmaf(c0[k].x, c1[k].x, dda);
            ddb = fmaf(c0[k].y, c1[k].y, ddb);
            ddc = fmaf(c0[k].z, c1[k].z, ddc);
            ddd = fmaf(c0[k].w, c1[k].w, ddd);
        }
        float s0 = (n0a + n0b) + (n0c + n0d);
        float s1 = (n1a + n1b) + (n1c + n1d);
        float sd = (dda + ddb) + (ddc + ddd);
        warp_sum3(s0, s1, sd);
        if (!lane) { sq[2 * warp] = s0; sq[2 * warp + 1] = s1; }
        diagdot = sd;
    }
    __syncthreads();                                  // sq[] visible

    if (!lane) {
        int i = 2 * warp, j = 2 * warp + 1;
        float d2v = sq[i] + sq[j] - 2.0f * diagdot;
        float d = sqrtf(fmaxf(d2v, 0.f));
        D[i * DS + j] = d;
        D[j * DS + i] = d;
    }

    // ---- gram off-diag: supertile rotation, 2x2 tiles ----
    {
        #pragma unroll 1
        for (int k = 1; k <= 8; k++) {
            if (k == 8 && warp >= 8) break;
            const int J = (warp + k) & 15;
            const float4* v0p = (const float4*)(rows + (2 * J) * CC);
            const float4* v1p = (const float4*)(rows + (2 * J + 1) * CC);
            float p00a=0,p00b=0,p00c=0,p00d=0;
            float p01a=0,p01b=0,p01c=0,p01d=0;
            float p10a=0,p10b=0,p10c=0,p10d=0;
            float p11a=0,p11b=0,p11c=0,p11d=0;
            #pragma unroll
            for (int q = 0; q < 8; q++) {
                float4 v0 = v0p[lane + 32 * q];
                float4 v1 = v1p[lane + 32 * q];
                p00a = fmaf(c0[q].x, v0.x, p00a);
                p00b = fmaf(c0[q].y, v0.y, p00b);
                p00c = fmaf(c0[q].z, v0.z, p00c);
                p00d = fmaf(c0[q].w, v0.w, p00d);
                p01a = fmaf(c0[q].x, v1.x, p01a);
                p01b = fmaf(c0[q].y, v1.y, p01b);
                p01c = fmaf(c0[q].z, v1.z, p01c);
                p01d = fmaf(c0[q].w, v1.w, p01d);
                p10a = fmaf(c1[q].x, v0.x, p10a);
                p10b = fmaf(c1[q].y, v0.y, p10b);
                p10c = fmaf(c1[q].z, v0.z, p10c);
                p10d = fmaf(c1[q].w, v0.w, p10d);
                p11a = fmaf(c1[q].x, v1.x, p11a);
                p11b = fmaf(c1[q].y, v1.y, p11b);
                p11c = fmaf(c1[q].z, v1.z, p11c);
                p11d = fmaf(c1[q].w, v1.w, p11d);
            }
            float s00 = (p00a + p00b) + (p00c + p00d);
            float s01 = (p01a + p01b) + (p01c + p01d);
            float s10 = (p10a + p10b) + (p10c + p10d);
            float s11 = (p11a + p11b) + (p11c + p11d);
            warp_sum4(s00, s01, s10, s11);
            if (!lane) {
                int i0 = 2 * warp, i1 = 2 * warp + 1, j0 = 2 * J, j1 = 2 * J + 1;
                float e00 = sqrtf(fmaxf(sq[i0] + sq[j0] - 2.0f * s00, 0.f));
                float e01 = sqrtf(fmaxf(sq[i0] + sq[j1] - 2.0f * s01, 0.f));
                float e10 = sqrtf(fmaxf(sq[i1] + sq[j0] - 2.0f * s10, 0.f));
                float e11 = sqrtf(fmaxf(sq[i1] + sq[j1] - 2.0f * s11, 0.f));
                D[i0 * DS + j0] = e00; D[j0 * DS + i0] = e00;
                D[i0 * DS + j1] = e01; D[j1 * DS + i0] = e01;
                D[i1 * DS + j0] = e10; D[j0 * DS + i1] = e10;
                D[i1 * DS + j1] = e11; D[j1 * DS + i1] = e11;
            }
        }
    }
    __syncthreads();                                  // D complete

    // ---- pre-loop argmin partials: warp w scans rows w and w+16 ----
    {
        u64 kk = 0xffffffffffffffffull;
        {
            unsigned kv = (lane > warp) ? __float_as_uint(D[warp * DS + lane]) : FULLM;
            unsigned wv = __reduce_min_sync(FULLM, kv);
            unsigned mm = __ballot_sync(FULLM, kv == wv);
            if (wv != FULLM) {
                int jw = __ffs(mm) - 1;
                kk = ((u64)wv << 32) | (unsigned)((warp << 5) | jw);
            }
        }
        {
            const int i = warp + 16;
            if (i <= NN - 2) {
                unsigned kv = (lane > i) ? __float_as_uint(D[i * DS + lane]) : FULLM;
                unsigned wv = __reduce_min_sync(FULLM, kv);
                unsigned mm = __ballot_sync(FULLM, kv == wv);
                if (wv != FULLM) {
                    int jw = __ffs(mm) - 1;
                    u64 kc = ((u64)wv << 32) | (unsigned)((i << 5) | jw);
                    kk = min(kk, kc);
                }
            }
        }
        if (!lane) { vals[warp] = (unsigned)(kk >> 32); idxs[warp] = (unsigned)(kk & 0x3ffu); }
    }
    __syncthreads();

    // ==== 31 merge steps, 2 barriers each ====
    int n = NN;
    int par = 0;
    int lpar = 0;
    int spare = 32;
    const int h0 = tid, h1 = tid + NT;
    for (int step = 0; step < NN - 1; step++, n--) {
        unsigned* vcur = vals + par * 32;
        unsigned* icur = idxs + par * 32;
        par ^= 1;
        unsigned* vnxt = vals + par * 32;
        unsigned* inxt = idxs + par * 32;
        int* Lcur = Lb + lpar * 32;
        lpar ^= 1;
        int* Lnxt = Lb + lpar * 32;

        // ---------- P1 ----------
        unsigned v  = (lane < 16) ? vcur[lane] : FULLM;
        unsigned gm = __reduce_min_sync(FULLM, v);
        unsigned mk = __ballot_sync(FULLM, v == gm);
        unsigned cd = ((mk >> lane) & 1) ? icur[lane] : FULLM;
        unsigned gi = __reduce_min_sync(FULLM, cd);

        const int a   = (gi >> 5) & 31;
        const int bbj = gi & 31;
        const int ra  = Lcur[a];
        const int rb  = Lcur[bbj];
        const int dst = spare;
        // freed slot: normally L[a]; when a==1 the reference's sequential
        // perm-sets drop logical row 0 and KEEP row 1, so freed slot is L[0].
        spare = (a == 1) ? Lcur[0] : ra;

        // conv1d(2ch->1ch,k=3,SAME)+bias+relu, TWO contiguous elems/thread
        // via float2 loads + neighbor-lane halo (exact conv1 chains).
        const float* Xa = rows + ra * CC;
        const float* Xb = rows + rb * CC;
        {
            const int hh = 2 * tid;                   // h = hh, hh+1
            const float2 fa = *(const float2*)(Xa + hh);
            const float2 fb = *(const float2*)(Xb + hh);
            float aL = __shfl_up_sync(FULLM, fa.y, 1);   // Xa[hh-1]
            float bL = __shfl_up_sync(FULLM, fb.y, 1);
            if (lane == 0) {
                aL = (hh > 0) ? Xa[hh - 1] : 0.f;
                bL = (hh > 0) ? Xb[hh - 1] : 0.f;
            }
            float aR = __shfl_down_sync(FULLM, fa.x, 1); // Xa[hh+2]
            float bR = __shfl_down_sync(FULLM, fb.x, 1);
            if (lane == 31) {
                aR = (hh + 2 < CC) ? Xa[hh + 2] : 0.f;
                bR = (hh + 2 < CC) ? Xb[hh + 2] : 0.f;
            }
            float2 mo;
            mo.x = conv1(aL,   fa.x, fa.y, bL,   fb.x, fb.y, w00,w01,w02,w10,w11,w12,bv);
            mo.y = conv1(fa.x, fa.y, aR,   fb.x, fb.y, bR,   w00,w01,w02,w10,w11,w12,bv);
            *(float2*)(rows + dst * CC + hh) = mo;    // no WAR: dst was spare
        }

        if (tid < n - 1) {
            int nv;
            if (tid == 0) nv = dst;
            else {
                int pp  = tid + 1;
                int src = (pp == a) ? 0 : ((pp == bbj) ? 1 : pp);
                nv = Lcur[src];
            }
            Lnxt[tid] = nv;
        }
        __syncthreads();                              // bar 1

        // ---------- P2: warps 0-9 dots (3 surv, m cached); 10-15 scan ----------
        const int cnt = n - 2;                        // survivors 1..cnt
        if (cnt > 0) {
            const int slv = (lane >= 1 && lane <= cnt) ? Lnxt[lane] : 0;
            u64 kk = 0xffffffffffffffffull;

            if (warp < 10) {
                const int j0 = 3 * warp;              // 0-based survivor idx
                if (j0 < cnt) {
                    const int c1ok = (j0 + 1) < cnt;
                    const int c2ok = (j0 + 2) < cnt;
                    const int s0 = __shfl_sync(FULLM, slv, 1 + j0);
                    const int s1 = __shfl_sync(FULLM, slv, c1ok ? (2 + j0) : (1 + j0));
                    const int s2 = __shfl_sync(FULLM, slv, c2ok ? (3 + j0) : (1 + j0));
                    // cache m row in registers
                    float4 mv[8];
                    const float4* rm = (const float4*)(rows + dst * CC);
                    #pragma unroll
                    for (int k = 0; k < 8; k++) mv[k] = rm[lane + 32 * k];

                    const float4* rs0 = (const float4*)(rows + s0 * CC);
                    const float4* rs1 = (const float4*)(rows + s1 * CC);
                    const float4* rs2 = (const float4*)(rows + s2 * CC);
                    float A0=0,A1=0,A2=0,A3=0;
                    float B0=0,B1=0,B2=0,B3=0;
                    float C0=0,C1=0,C2=0,C3=0;
                    float M0=0,M1=0,M2=0,M3=0;
                    #pragma unroll
                    for (int k = 0; k < 8; k++) {
                        float4 u  = mv[k];
                        float4 v0 = rs0[lane + 32 * k];
                        float4 v1 = rs1[lane + 32 * k];
                        float4 v2 = rs2[lane + 32 * k];
                        A0 = fmaf(u.x, v0.x, A0);
                        A1 = fmaf(u.y, v0.y, A1);
                        A2 = fmaf(u.z, v0.z, A2);
                        A3 = fmaf(u.w, v0.w, A3);
                        B0 = fmaf(u.x, v1.x, B0);
                        B1 = fmaf(u.y, v1.y, B1);
                        B2 = fmaf(u.z, v1.z, B2);
                        B3 = fmaf(u.w, v1.w, B3);
                        C0 = fmaf(u.x, v2.x, C0);
                        C1 = fmaf(u.y, v2.y, C1);
                        C2 = fmaf(u.z, v2.z, C2);
                        C3 = fmaf(u.w, v2.w, C3);
                        M0 = fmaf(u.x, u.x, M0);
                        M1 = fmaf(u.y, u.y, M1);
                        M2 = fmaf(u.z, u.z, M2);
                        M3 = fmaf(u.w, u.w, M3);
                    }
                    float d0  = (A0 + A1) + (A2 + A3);
                    float d1  = (B0 + B1) + (B2 + B3);
                    float d2s = (C0 + C1) + (C2 + C3);
                    float msq = (M0 + M1) + (M2 + M3);
                    warp_sum4(d0, d1, d2s, msq);
                    if (!lane) {
                        float e0 = sqrtf(fmaxf(msq + sq[s0] - 2.0f * d0, 0.f));
                        D[dst * DS + s0] = e0;
                        D[s0 * DS + dst] = e0;
                        kk = ((u64)__float_as_uint(e0) << 32) | (unsigned)(1 + j0);
                        if (c1ok) {
                            float e1 = sqrtf(fmaxf(msq + sq[s1] - 2.0f * d1, 0.f));
                            D[dst * DS + s1] = e1;
                            D[s1 * DS + dst] = e1;
                            u64 k1 = ((u64)__float_as_uint(e1) << 32) | (unsigned)(2 + j0);
                            kk = min(kk, k1);
                        }
                        if (c2ok) {
                            float e2 = sqrtf(fmaxf(msq + sq[s2] - 2.0f * d2s, 0.f));
                            D[dst * DS + s2] = e2;
                            D[s2 * DS + dst] = e2;
                            u64 k2 = ((u64)__float_as_uint(e2) << 32) | (unsigned)(3 + j0);
                            kk = min(kk, k2);
                        }
                        if (warp == 0) sq[dst] = msq; // persist merged norm
                    }
                }
            } else {
                // scan warps: rows i = (warp-10)+1 + 6r, r=0..4 (flat, independent)
                #pragma unroll
                for (int r = 0; r < 5; r++) {
                    const int i = (warp - 10) + 1 + 6 * r;
                    if (i <= cnt - 1) {
                        const int si = __shfl_sync(FULLM, slv, i);
                        unsigned kv = FULLM;
                        if (lane > i && lane <= cnt)
                            kv = __float_as_uint(D[si * DS + slv]);
                        unsigned wv = __reduce_min_sync(FULLM, kv);
                        unsigned mm = __ballot_sync(FULLM, kv == wv);
                        if (wv != FULLM) {
                            int jw = __ffs(mm) - 1;
                            u64 kc = ((u64)wv << 32) | (unsigned)((i << 5) | jw);
                            kk = min(kk, kc);
                        }
                    }
                }
            }

            if (!lane) {
                vnxt[warp] = (unsigned)(kk >> 32);
                inxt[warp] = (unsigned)(kk & 0x3ffu);
            }
        }
        __syncthreads();                              // bar 2
    }

    // final merged row lives at slot Lfinal[0]
    {
        const int fs = (Lb + lpar * 32)[0];
        out[(size_t)b * CC + h0] = rows[fs * CC + h0];
        out[(size_t)b * CC + h1] = rows[fs * CC + h1];
    }
}

extern "C" void kernel_launch(void* const* d_in, const int* in_sizes, int n_in,
                              void* d_out, int out_size)
{
    const float* x  = (const float*)d_in[0];
    const float* cw = (const float*)d_in[1];
    const float* cb = (const float*)d_in[2];
    float* out = (float*)d_out;

    int B = in_sizes[0] / (NN * CC);

    cudaFuncSetAttribute(merge_tree_kernel,
                         cudaFuncAttributeMaxDynamicSharedMemorySize,
                         SMEM_TOTAL);
    merge_tree_kernel<<<B, NT, SMEM_TOTAL>>>(x, cw, cb, out);
}